// round 6
// baseline (speedup 1.0000x reference)
#include <cuda_runtime.h>

// activation_moduleA: out[0:SIZE] = p = x[0:SIZE]
//                     out[SIZE:N] = weight * selu(p) + q,  q = x[SIZE:N]
// selu(v) = SCALE * (v > 0 ? v : ALPHA*(exp(v)-1))
//
// HBM-streaming kernel at the bandwidth wall. R4: R2's max-occupancy shape
// (1 float4-tile per thread, regs ~31, occ ~81%) + evict-first streaming
// stores (__stcs) to keep output write-allocate traffic out of L2's way.

#define SELU_SCALE 1.0507009873554804934193349852946f
#define SELU_ALPHA 1.6732632423543772848170429916717f

#define TPB 256

__device__ __forceinline__ float selu_f(float v) {
    float neg = SELU_ALPHA * expm1f(v);
    return SELU_SCALE * (v > 0.0f ? v : neg);
}

__global__ void __launch_bounds__(TPB)
activation_kernel(const float4* __restrict__ x,
                  const float4* __restrict__ w,
                  float4* __restrict__ out,
                  int size4)   // SIZE/4 float4 elements per half
{
    int i = blockIdx.x * TPB + threadIdx.x;
    if (i >= size4) return;

    float4 p  = x[i];
    float4 q  = x[i + size4];
    float4 wv = w[i];

    // first half: straight copy of p (issue store early, evict-first)
    __stcs(&out[i], p);

    float4 r;
    r.x = fmaf(wv.x, selu_f(p.x), q.x);
    r.y = fmaf(wv.y, selu_f(p.y), q.y);
    r.z = fmaf(wv.z, selu_f(p.z), q.z);
    r.w = fmaf(wv.w, selu_f(p.w), q.w);
    __stcs(&out[i + size4], r);
}

extern "C" void kernel_launch(void* const* d_in, const int* in_sizes, int n_in,
                              void* d_out, int out_size) {
    const float* x = (const float*)d_in[0];
    const float* w = (const float*)d_in[1];
    float* out = (float*)d_out;

    const int N = in_sizes[0];          // 33554432
    const int SIZE = N / 2;             // 16777216
    const int size4 = SIZE / 4;         // 4194304 float4 per half

    const int blocks = (size4 + TPB - 1) / TPB;    // 16384
    activation_kernel<<<blocks, TPB>>>(
        (const float4*)x, (const float4*)w, (float4*)out, size4);
}

// round 9
// speedup vs baseline: 1.0114x; 1.0114x over previous
#include <cuda_runtime.h>

// activation_moduleA: out[0:SIZE] = p = x[0:SIZE]
//                     out[SIZE:N] = weight * selu(p) + q,  q = x[SIZE:N]
// selu(v) = SCALE * (v > 0 ? v : ALPHA*(exp(v)-1))
//
// R8: back to the proven best shape (R2: plain LDG/STG float4, 1 tile per
// thread, regs ~31, occ ~81%, DRAM 81.5%). Single variation: TPB=512
// (8192 CTAs) to reduce CTA scheduling overhead at the same occupancy.
// The evict-hint experiments (R6/R7) failed to compile/run; the op is at
// the HBM streaming wall (~6.4 TB/s effective, ~320 MB mandatory traffic).

#define SELU_SCALE 1.0507009873554804934193349852946f
#define SELU_ALPHA 1.6732632423543772848170429916717f

#define TPB 512

__device__ __forceinline__ float selu_f(float v) {
    float neg = SELU_ALPHA * expm1f(v);
    return SELU_SCALE * (v > 0.0f ? v : neg);
}

__global__ void __launch_bounds__(TPB)
activation_kernel(const float4* __restrict__ x,
                  const float4* __restrict__ w,
                  float4* __restrict__ out,
                  int size4)   // SIZE/4 float4 elements per half
{
    int i = blockIdx.x * TPB + threadIdx.x;
    if (i >= size4) return;

    float4 p  = x[i];
    float4 q  = x[i + size4];
    float4 wv = w[i];

    // first half: straight copy of p (store issues while SELU computes)
    out[i] = p;

    float4 r;
    r.x = fmaf(wv.x, selu_f(p.x), q.x);
    r.y = fmaf(wv.y, selu_f(p.y), q.y);
    r.z = fmaf(wv.z, selu_f(p.z), q.z);
    r.w = fmaf(wv.w, selu_f(p.w), q.w);
    out[i + size4] = r;
}

extern "C" void kernel_launch(void* const* d_in, const int* in_sizes, int n_in,
                              void* d_out, int out_size) {
    const float* x = (const float*)d_in[0];
    const float* w = (const float*)d_in[1];
    float* out = (float*)d_out;

    const int N = in_sizes[0];          // 33554432
    const int SIZE = N / 2;             // 16777216
    const int size4 = SIZE / 4;         // 4194304 float4 per half

    const int blocks = (size4 + TPB - 1) / TPB;    // 8192
    activation_kernel<<<blocks, TPB>>>(
        (const float4*)x, (const float4*)w, (float4*)out, size4);
}

// round 10
// speedup vs baseline: 1.0187x; 1.0073x over previous
#include <cuda_runtime.h>

// activation_moduleA: out[0:SIZE] = p = x[0:SIZE]
//                     out[SIZE:N] = weight * selu(p) + q,  q = x[SIZE:N]
// selu(v) = SCALE * (v > 0 ? v : ALPHA*(exp(v)-1))
//
// CONVERGED: this op is HBM-streaming-bound (~320 MB mandatory traffic,
// ~6.3 TB/s effective on the 5-stream mixed R/W pattern). R2/R3/R8 shapes
// all measured 53.3-54.0 us. Final shape: TPB=512, one float4-tile per
// thread, plain LDG/STG (cache hints measured neutral-to-negative),
// guard-free exact-division path (8192*512 == size4).

#define SELU_SCALE 1.0507009873554804934193349852946f
#define SELU_ALPHA 1.6732632423543772848170429916717f

#define TPB 512

__device__ __forceinline__ float selu_f(float v) {
    float neg = SELU_ALPHA * expm1f(v);
    return SELU_SCALE * (v > 0.0f ? v : neg);
}

template <bool GUARD>
__global__ void __launch_bounds__(TPB)
activation_kernel(const float4* __restrict__ x,
                  const float4* __restrict__ w,
                  float4* __restrict__ out,
                  int size4)   // SIZE/4 float4 elements per half
{
    int i = blockIdx.x * TPB + threadIdx.x;
    if (GUARD && i >= size4) return;

    float4 p  = x[i];
    float4 q  = x[i + size4];
    float4 wv = w[i];

    // first half: straight copy of p (store issues while SELU computes)
    out[i] = p;

    float4 r;
    r.x = fmaf(wv.x, selu_f(p.x), q.x);
    r.y = fmaf(wv.y, selu_f(p.y), q.y);
    r.z = fmaf(wv.z, selu_f(p.z), q.z);
    r.w = fmaf(wv.w, selu_f(p.w), q.w);
    out[i + size4] = r;
}

extern "C" void kernel_launch(void* const* d_in, const int* in_sizes, int n_in,
                              void* d_out, int out_size) {
    const float* x = (const float*)d_in[0];
    const float* w = (const float*)d_in[1];
    float* out = (float*)d_out;

    const int N = in_sizes[0];          // 33554432
    const int SIZE = N / 2;             // 16777216
    const int size4 = SIZE / 4;         // 4194304 float4 per half

    if (size4 % TPB == 0) {
        // exact division: no per-thread bounds guard (hit for this problem)
        activation_kernel<false><<<size4 / TPB, TPB>>>(
            (const float4*)x, (const float4*)w, (float4*)out, size4);
    } else {
        activation_kernel<true><<<(size4 + TPB - 1) / TPB, TPB>>>(
            (const float4*)x, (const float4*)w, (float4*)out, size4);
    }
}